// round 2
// baseline (speedup 1.0000x reference)
#include <cuda_runtime.h>
#include <cstring>

#define DINLINE __device__ __forceinline__

// ---------- packed fp32x2 helpers (exact fp32 semantics, 2x rate) ----------
DINLINE float2 ffma2(float2 a, float2 b, float2 c) {
    unsigned long long au, bu, cu, ru;
    memcpy(&au, &a, 8); memcpy(&bu, &b, 8); memcpy(&cu, &c, 8);
    asm("fma.rn.f32x2 %0, %1, %2, %3;" : "=l"(ru) : "l"(au), "l"(bu), "l"(cu));
    float2 r; memcpy(&r, &ru, 8); return r;
}
DINLINE float2 fadd2(float2 a, float2 b) {
    unsigned long long au, bu, ru;
    memcpy(&au, &a, 8); memcpy(&bu, &b, 8);
    asm("add.rn.f32x2 %0, %1, %2;" : "=l"(ru) : "l"(au), "l"(bu));
    float2 r; memcpy(&r, &ru, 8); return r;
}
DINLINE float f4get(float4 v, int i) { return i == 0 ? v.x : i == 1 ? v.y : i == 2 ? v.z : v.w; }

// ---------- scratch (static device globals; no allocs) ----------
__device__ unsigned long long g_grid64[32 * 64 * 64];            // 1 MB bitmask: [b][z][y], bit = x
__device__ float g_x1[(size_t)32 * 32 * 32 * 32 * 16];           // 67 MB  [b][z][y][x][c16]
__device__ float g_x2[(size_t)32 * 8 * 16 * 16 * 16 * 4];        // 16.8MB [b][c4grp(8)][z][y][x][4ch]
__device__ float g_feat[(size_t)32 * 32768];                     // 4.2 MB [b][c*512 + z*64+y*8+x]

// ---------- kernel 0: clear grid ----------
__global__ void clear_grid() {
    int i = blockIdx.x * 256 + threadIdx.x;
    ((ulonglong2*)g_grid64)[i] = make_ulonglong2(0ull, 0ull);
}

// ---------- kernel 1: scatter points into bitmask ----------
__global__ void scatter_kernel(const float* __restrict__ pc) {
    int t = blockIdx.x * 256 + threadIdx.x;            // 524288 = 32*16384
    float px = pc[t * 3 + 0];
    float py = pc[t * 3 + 1];
    float pz = pc[t * 3 + 2];
    int b = t >> 14;
    int cx = (int)(((px + 1.0f) * 0.5f) * 63.0f); cx = min(max(cx, 0), 63);
    int cy = (int)(((py + 1.0f) * 0.5f) * 63.0f); cy = min(max(cy, 0), 63);
    int cz = (int)(((pz + 1.0f) * 0.5f) * 63.0f); cz = min(max(cz, 0), 63);
    atomicOr(&g_grid64[(b * 64 + cz) * 64 + cy], 1ull << cx);
}

// ---------- kernel 2: conv1 (1->16, 64^3 -> 32^3), binary input ----------
__global__ void conv1_kernel(const float* __restrict__ w1, const float* __restrict__ b1) {
    __shared__ float2 sw[27 * 8];
    __shared__ float2 sb[8];
    int tid = threadIdx.x;
    for (int j = tid; j < 216; j += 256) {
        int cp = j & 7, tap = j >> 3;
        sw[j] = make_float2(w1[(2 * cp) * 27 + tap], w1[(2 * cp + 1) * 27 + tap]);
    }
    if (tid < 8) sb[tid] = make_float2(b1[2 * tid], b1[2 * tid + 1]);
    __syncthreads();

    int idx = blockIdx.x * 256 + tid;                  // 1,048,576
    int x = idx & 31, y = (idx >> 5) & 31, z = (idx >> 10) & 31, b = idx >> 15;

    float2 acc[8];
#pragma unroll
    for (int j = 0; j < 8; j++) acc[j] = sb[j];

#pragma unroll 1
    for (int kz = 0; kz < 3; kz++) {
        int iz = 2 * z - 1 + kz;
        if ((unsigned)iz >= 64u) continue;
#pragma unroll 1
        for (int ky = 0; ky < 3; ky++) {
            int iy = 2 * y - 1 + ky;
            if ((unsigned)iy >= 64u) continue;
            unsigned long long m = g_grid64[(b * 64 + iz) * 64 + iy];
            if (!m) continue;
            int tapb = (kz * 3 + ky) * 3;
#pragma unroll 1
            for (int kx = 0; kx < 3; kx++) {
                int ix = 2 * x - 1 + kx;
                if ((unsigned)ix < 64u && ((m >> ix) & 1ull)) {
                    const float2* wv = &sw[(tapb + kx) * 8];
#pragma unroll
                    for (int j = 0; j < 8; j++) acc[j] = fadd2(acc[j], wv[j]);
                }
            }
        }
    }
    float2* outp = (float2*)(g_x1 + (size_t)idx * 16);
#pragma unroll
    for (int j = 0; j < 8; j++) {
        float2 v = acc[j];
        v.x = fmaxf(v.x, 0.0f); v.y = fmaxf(v.y, 0.0f);
        outp[j] = v;
    }
}

// ---------- kernel 3: conv2 (16->32, 32^3 -> 16^3), smem-staged ----------
// block = (b, z, oh, yh); 128 threads = 16x * 8y; thread = 1 voxel x 16 och.
// smem: weights [tap27][in16][op8] float2 (27.6KB) + tile [ch16][iy17][ix33] (35.9KB)
__global__ void __launch_bounds__(128) conv2_kernel(const float* __restrict__ w2,
                                                    const float* __restrict__ b2) {
    extern __shared__ float smem_raw[];
    float2* sw    = (float2*)smem_raw;                 // 3456 float2 [tap][in][op]
    float2* sbias = (float2*)(smem_raw + 6912);        // 8 float2
    float*  tile  = smem_raw + 6928;                   // 16*17*33 = 8976 floats

    int tid = threadIdx.x;
    int bid = blockIdx.x;                              // 2048 = 32b*16z*2oh*2yh
    int yh = bid & 1, oh = (bid >> 1) & 1, z = (bid >> 2) & 15, b = bid >> 6;
    int o0 = oh * 16;

    for (int j = tid; j < 3456; j += 128) {
        int op = j & 7, in = (j >> 3) & 15, tap = j >> 7;
        sw[j] = make_float2(w2[((o0 + 2 * op) * 16 + in) * 27 + tap],
                            w2[((o0 + 2 * op + 1) * 16 + in) * 27 + tap]);
    }
    if (tid < 8) sbias[tid] = make_float2(b2[o0 + 2 * tid], b2[o0 + 2 * tid + 1]);
    // zero left-pad column of tile (ixp = 0)
    for (int j = tid; j < 16 * 17; j += 128) {
        int ch = j / 17, iyl = j % 17;
        tile[ch * 561 + iyl * 33] = 0.0f;
    }

    int x = tid & 15, yl = tid >> 4;
    int iy0 = 16 * yh - 1;

    float2 acc[8];
#pragma unroll
    for (int op = 0; op < 8; op++) acc[op] = __ldg((const float2*)0) , acc[op] = acc[op]; // placeholder (overwritten below)
#pragma unroll
    for (int op = 0; op < 8; op++) acc[op] = make_float2(b2[o0 + 2 * op], b2[o0 + 2 * op + 1]);

    const float* x1b = g_x1 + (size_t)b * (32 * 32 * 32 * 16);

#pragma unroll 1
    for (int kz = 0; kz < 3; kz++) {
        int iz = 2 * z - 1 + kz;
        if ((unsigned)iz >= 32u) continue;             // uniform across block (z per block)
        __syncthreads();
        // stage plane: 17 rows x 32 ix x 16 ch, coalesced float4 reads
        const float* plane = x1b + (size_t)iz * (32 * 32 * 16);
        for (int it = 0; it < 17; it++) {
            int idx = it * 128 + tid;                  // < 2176
            int ch4 = idx & 3;
            int ix  = (idx >> 2) & 31;
            int iyl = idx >> 7;                        // 0..16
            int iy  = iy0 + iyl;
            float4 v = make_float4(0.f, 0.f, 0.f, 0.f);
            if ((unsigned)iy < 32u) v = ((const float4*)(plane + ((size_t)iy * 32 + ix) * 16))[ch4];
            float* t = tile + (ch4 * 4) * 561 + iyl * 33 + (ix + 1);
            t[0]       = v.x;
            t[561]     = v.y;
            t[1122]    = v.z;
            t[1683]    = v.w;
        }
        __syncthreads();

#pragma unroll 1
        for (int ky = 0; ky < 3; ky++) {
            int iyl = 2 * yl + ky;                     // always in [0,16]; OOB rows are zero
            int tapb = (kz * 3 + ky) * 3;
#pragma unroll 1
            for (int kx = 0; kx < 3; kx++) {
                int ixp = 2 * x + kx;                  // [0,32]; ixp=0 column is zero
                const float* trow = tile + iyl * 33 + ixp;
                const float2* wt = sw + (tapb + kx) * 128;
#pragma unroll
                for (int in = 0; in < 16; in++) {
                    float a = trow[in * 561];
                    float2 av = make_float2(a, a);
                    const float4* wi = (const float4*)(wt + in * 8);
                    float4 w0 = wi[0], w1 = wi[1], w2v = wi[2], w3v = wi[3];
                    acc[0] = ffma2(av, make_float2(w0.x, w0.y), acc[0]);
                    acc[1] = ffma2(av, make_float2(w0.z, w0.w), acc[1]);
                    acc[2] = ffma2(av, make_float2(w1.x, w1.y), acc[2]);
                    acc[3] = ffma2(av, make_float2(w1.z, w1.w), acc[3]);
                    acc[4] = ffma2(av, make_float2(w2v.x, w2v.y), acc[4]);
                    acc[5] = ffma2(av, make_float2(w2v.z, w2v.w), acc[5]);
                    acc[6] = ffma2(av, make_float2(w3v.x, w3v.y), acc[6]);
                    acc[7] = ffma2(av, make_float2(w3v.z, w3v.w), acc[7]);
                }
            }
        }
    }

    // store: x2 layout [b][g8][pos4096][4ch], groups g = oh*4 + q
    int y = yh * 8 + yl;
    int pos = (z * 16 + y) * 16 + x;
    float4* x2o = (float4*)g_x2 + ((size_t)b * 8 + oh * 4) * 4096 + pos;
#pragma unroll
    for (int q = 0; q < 4; q++) {
        float4 v = make_float4(fmaxf(acc[2 * q].x, 0.f), fmaxf(acc[2 * q].y, 0.f),
                               fmaxf(acc[2 * q + 1].x, 0.f), fmaxf(acc[2 * q + 1].y, 0.f));
        x2o[(size_t)q * 4096] = v;
    }
}

// ---------- kernel 4: conv3 (32->64, 16^3 -> 8^3), gather on [g][pos][4] layout ----------
// block = (b, zh4, oq4); 128 threads = 8x*8y*2zt; thread = 1 voxel x 16 och.
__global__ void __launch_bounds__(128) conv3_kernel(const float* __restrict__ w3,
                                                    const float* __restrict__ b3) {
    extern __shared__ float smem_raw[];
    float2* sw    = (float2*)smem_raw;                 // 6912 float2 [tap][in32][op8]
    float2* sbias = (float2*)(smem_raw + 13824);       // 8 float2

    int tid = threadIdx.x;
    int bid = blockIdx.x;                              // 512 = 32b*4zh*4oq
    int oq = bid & 3, zh = (bid >> 2) & 3, b = bid >> 4;
    int o0 = oq * 16;

    for (int j = tid; j < 6912; j += 128) {
        int op = j & 7, in = (j >> 3) & 31, tap = j >> 8;
        sw[j] = make_float2(w3[((o0 + 2 * op) * 32 + in) * 27 + tap],
                            w3[((o0 + 2 * op + 1) * 32 + in) * 27 + tap]);
    }
    if (tid < 8) sbias[tid] = make_float2(b3[o0 + 2 * tid], b3[o0 + 2 * tid + 1]);
    __syncthreads();

    int x = tid & 7, y = (tid >> 3) & 7, zt = tid >> 6;
    int z = zh * 2 + zt;

    float2 acc[8];
#pragma unroll
    for (int op = 0; op < 8; op++) acc[op] = sbias[op];

    const float4* x2b = (const float4*)g_x2 + (size_t)b * 8 * 4096;

#pragma unroll 1
    for (int kz = 0; kz < 3; kz++) {
        int iz = 2 * z - 1 + kz;
        if ((unsigned)iz >= 16u) continue;
#pragma unroll 1
        for (int ky = 0; ky < 3; ky++) {
            int iy = 2 * y - 1 + ky;
            if ((unsigned)iy >= 16u) continue;
            int rowbase = (iz * 16 + iy) * 16;
#pragma unroll 1
            for (int kx = 0; kx < 3; kx++) {
                int ix = 2 * x - 1 + kx;               // max 15
                bool valid = (ix >= 0);
                int jx = valid ? ix : 0;
                float4 A[8];
#pragma unroll
                for (int g = 0; g < 8; g++) A[g] = x2b[(size_t)g * 4096 + rowbase + jx];
                if (!valid) {
#pragma unroll
                    for (int g = 0; g < 8; g++) A[g] = make_float4(0.f, 0.f, 0.f, 0.f);
                }
                const float2* wt = sw + ((kz * 3 + ky) * 3 + kx) * 256;
#pragma unroll
                for (int g = 0; g < 8; g++) {
#pragma unroll
                    for (int ii = 0; ii < 4; ii++) {
                        float a = f4get(A[g], ii);
                        float2 av = make_float2(a, a);
                        const float4* wi = (const float4*)(wt + (g * 4 + ii) * 8);
                        float4 w0 = wi[0], w1 = wi[1], w2v = wi[2], w3v = wi[3];
                        acc[0] = ffma2(av, make_float2(w0.x, w0.y), acc[0]);
                        acc[1] = ffma2(av, make_float2(w0.z, w0.w), acc[1]);
                        acc[2] = ffma2(av, make_float2(w1.x, w1.y), acc[2]);
                        acc[3] = ffma2(av, make_float2(w1.z, w1.w), acc[3]);
                        acc[4] = ffma2(av, make_float2(w2v.x, w2v.y), acc[4]);
                        acc[5] = ffma2(av, make_float2(w2v.z, w2v.w), acc[5]);
                        acc[6] = ffma2(av, make_float2(w3v.x, w3v.y), acc[6]);
                        acc[7] = ffma2(av, make_float2(w3v.z, w3v.w), acc[7]);
                    }
                }
            }
        }
    }

    // write relu'd into flattened feat [b][c*512 + s]; lanes coalesce over s
    int s = z * 64 + y * 8 + x;
    float* fbase = g_feat + (size_t)b * 32768;
#pragma unroll
    for (int op = 0; op < 8; op++) {
        int c0 = o0 + 2 * op;
        fbase[(size_t)c0 * 512 + s]       = fmaxf(acc[op].x, 0.f);
        fbase[(size_t)(c0 + 1) * 512 + s] = fmaxf(acc[op].y, 0.f);
    }
}

// ---------- kernel 5: FC (32 x 128 <- 32768) ----------
__global__ void fc_kernel(const float* __restrict__ fcw, const float* __restrict__ fcb,
                          float* __restrict__ out) {
    int t = threadIdx.x;                                // 512
    int bg = blockIdx.x;                                // 8
    int lc = blockIdx.y;                                // 16
    int bl = t >> 7;
    int b = bg * 4 + bl;
    int fl = t & 127;
    int l0 = lc * 8;

    float p[8] = {0.f, 0.f, 0.f, 0.f, 0.f, 0.f, 0.f, 0.f};
    const float4* fv = (const float4*)(g_feat + (size_t)b * 32768);
#pragma unroll 1
    for (int k = fl; k < 8192; k += 128) {
        float4 a = fv[k];
#pragma unroll
        for (int j = 0; j < 8; j++) {
            float4 w = ((const float4*)(fcw + (size_t)(l0 + j) * 32768))[k];
            p[j] += a.x * w.x + a.y * w.y + a.z * w.z + a.w * w.w;
        }
    }
#pragma unroll
    for (int j = 0; j < 8; j++) {
        float v = p[j];
        for (int off = 16; off > 0; off >>= 1) v += __shfl_xor_sync(0xffffffffu, v, off);
        p[j] = v;
    }
    __shared__ float sh[16][8];
    int warp = t >> 5, lane = t & 31;
    if (lane == 0) {
#pragma unroll
        for (int j = 0; j < 8; j++) sh[warp][j] = p[j];
    }
    __syncthreads();
    if (t < 32) {
        int blb = t >> 3, j = t & 7;
        float s = sh[blb * 4 + 0][j] + sh[blb * 4 + 1][j] + sh[blb * 4 + 2][j] + sh[blb * 4 + 3][j];
        out[(size_t)(bg * 4 + blb) * 128 + l0 + j] = s + fcb[l0 + j];
    }
}

// ---------- launch ----------
extern "C" void kernel_launch(void* const* d_in, const int* in_sizes, int n_in,
                              void* d_out, int out_size) {
    (void)in_sizes; (void)n_in; (void)out_size;
    const float* pc  = (const float*)d_in[0];
    const float* w1  = (const float*)d_in[1];
    const float* b1  = (const float*)d_in[2];
    const float* w2  = (const float*)d_in[3];
    const float* b2  = (const float*)d_in[4];
    const float* w3  = (const float*)d_in[5];
    const float* b3  = (const float*)d_in[6];
    const float* fcw = (const float*)d_in[7];
    const float* fcb = (const float*)d_in[8];
    float* out = (float*)d_out;

    cudaFuncSetAttribute(conv2_kernel, cudaFuncAttributeMaxDynamicSharedMemorySize, 63616);
    cudaFuncSetAttribute(conv3_kernel, cudaFuncAttributeMaxDynamicSharedMemorySize, 55424);

    clear_grid<<<256, 256>>>();
    scatter_kernel<<<2048, 256>>>(pc);
    conv1_kernel<<<4096, 256>>>(w1, b1);
    conv2_kernel<<<2048, 128, 63616>>>(w2, b2);
    conv3_kernel<<<512, 128, 55424>>>(w3, b3);
    fc_kernel<<<dim3(8, 16), 512>>>(fcw, fcb, out);
}